// round 13
// baseline (speedup 1.0000x reference)
#include <cuda_runtime.h>
#include <cuda_fp16.h>
#include <mma.h>
#include <math.h>
#include <cstdint>

using namespace nvcuda;

#define LN_EPS 1e-7f

__device__ float g_XGf[(size_t)16384 * 2048];
__device__ float g_XGb[(size_t)16384 * 2048];
__device__ uint32_t g_ENC32[(size_t)16 * 1024 * 1024];  // (tag<<16)|fp16 h
__device__ float g_FEATP[512 * 1024];
__device__ float g_FEAT [512 * 1024];
__device__ float g_Qm[512 * 1024];
__device__ float g_Km[512 * 1024];
__device__ float g_Vm[512 * 1024];
__device__ float g_CTX[512 * 1024];
__device__ float g_TMP[512 * 1024];
__device__ float g_ATT[512 * 1024];

// fp16 operand staging
__device__ __half g_HS16[(size_t)16384 * 1024];
__device__ __half g_WF16[(size_t)2048 * 1024];
__device__ __half g_WB16[(size_t)2048 * 1024];
__device__ __half g_WQ16[(size_t)1024 * 1024];
__device__ __half g_WK16[(size_t)1024 * 1024];
__device__ __half g_WV16[(size_t)1024 * 1024];
__device__ __half g_WO16[(size_t)1024 * 1024];
__device__ __half g_F16 [(size_t)512 * 1024];
__device__ __half g_C16 [(size_t)512 * 1024];

// ---------------- clear ENC tags (every replay; keeps dataflow honest) ----------------
__global__ __launch_bounds__(256) void zero_enc()
{
    const size_t i = ((size_t)blockIdx.x * 256 + threadIdx.x) * 8;
    uint4 z = make_uint4(0u, 0u, 0u, 0u);
    *(uint4*)(g_ENC32 + i)     = z;
    *(uint4*)(g_ENC32 + i + 4) = z;
}

// ---------------- fp32 -> fp16 conversion ----------------
__global__ __launch_bounds__(256) void f2h(
    const float* __restrict__ x, __half* __restrict__ y, int n)
{
    const int i = (blockIdx.x * 256 + threadIdx.x) * 8;
    if (i >= n) return;
    const float4 a = *(const float4*)(x + i);
    const float4 b = *(const float4*)(x + i + 4);
    union { __half2 h2[4]; float4 v; } u;
    u.h2[0] = __floats2half2_rn(a.x, a.y);
    u.h2[1] = __floats2half2_rn(a.z, a.w);
    u.h2[2] = __floats2half2_rn(b.x, b.y);
    u.h2[3] = __floats2half2_rn(b.z, b.w);
    *(float4*)(y + i) = u.v;
}

// =====================================================================
// fp16 tensor GEMM (R11 version: cp.async, 2 CTAs/SM)
// =====================================================================
#define HLD 72
#define LDC 132
#define STG_A0 0
#define STG_B0 18432
#define STG_A1 36864
#define STG_B1 55296

__global__ __launch_bounds__(256, 2) void gemm_h(
    const __half* __restrict__ A, const __half* __restrict__ B,
    const float* __restrict__ bias, float* __restrict__ C,
    int M, int N, int K)
{
    extern __shared__ char smem[];
    float* Co = (float*)smem;

    const int tid = threadIdx.x;
    const int wid = tid >> 5;
    const int brow = blockIdx.y * 128;
    const int bcol = blockIdx.x * 128;
    const int wm = (wid & 3) * 32;
    const int wn = (wid >> 2) * 64;

    const __half* Ag = A + (size_t)brow * K;
    const __half* Bg = B + (size_t)bcol * K;

    wmma::fragment<wmma::accumulator, 16, 16, 16, float> acc[2][4];
#pragma unroll
    for (int i = 0; i < 2; ++i)
#pragma unroll
        for (int j = 0; j < 4; ++j) wmma::fill_fragment(acc[i][j], 0.f);

    auto issue_stage = [&](int aoff, int boff, int kt) {
#pragma unroll
        for (int p = 0; p < 4; ++p) {
            const int idx = tid + p * 256;
            const int r = idx >> 3, c = (idx & 7) * 8;
            const unsigned da = (unsigned)__cvta_generic_to_shared(
                smem + aoff + (r * HLD + c) * 2);
            const unsigned db = (unsigned)__cvta_generic_to_shared(
                smem + boff + (r * HLD + c) * 2);
            asm volatile("cp.async.cg.shared.global [%0], [%1], 16;"
                         :: "r"(da), "l"(Ag + (size_t)r * K + kt + c));
            asm volatile("cp.async.cg.shared.global [%0], [%1], 16;"
                         :: "r"(db), "l"(Bg + (size_t)r * K + kt + c));
        }
    };

    issue_stage(STG_A0, STG_B0, 0);
    asm volatile("cp.async.commit_group;");

    int buf = 0;
    for (int kt = 0; kt < K; kt += 64) {
        if (kt + 64 < K)
            issue_stage(buf ? STG_A0 : STG_A1, buf ? STG_B0 : STG_B1, kt + 64);
        asm volatile("cp.async.commit_group;");
        asm volatile("cp.async.wait_group 1;");
        __syncthreads();

        const __half* As = (const __half*)(smem + (buf ? STG_A1 : STG_A0));
        const __half* Bs = (const __half*)(smem + (buf ? STG_B1 : STG_B0));
#pragma unroll
        for (int kk = 0; kk < 64; kk += 16) {
            wmma::fragment<wmma::matrix_a, 16, 16, 16, __half, wmma::row_major> af[2];
            wmma::fragment<wmma::matrix_b, 16, 16, 16, __half, wmma::col_major> bf[4];
#pragma unroll
            for (int i = 0; i < 2; ++i)
                wmma::load_matrix_sync(af[i], As + (wm + i * 16) * HLD + kk, HLD);
#pragma unroll
            for (int j = 0; j < 4; ++j)
                wmma::load_matrix_sync(bf[j], Bs + (wn + j * 16) * HLD + kk, HLD);
#pragma unroll
            for (int i = 0; i < 2; ++i)
#pragma unroll
                for (int j = 0; j < 4; ++j)
                    wmma::mma_sync(acc[i][j], af[i], bf[j], acc[i][j]);
        }
        __syncthreads();
        buf ^= 1;
    }

#pragma unroll
    for (int i = 0; i < 2; ++i)
#pragma unroll
        for (int j = 0; j < 4; ++j)
            wmma::store_matrix_sync(Co + (wm + i * 16) * LDC + wn + j * 16,
                                    acc[i][j], LDC, wmma::mem_row_major);
    __syncthreads();

    for (int idx = tid; idx < 128 * 32; idx += 256) {
        const int r = idx >> 5, c4 = (idx & 31) * 4;
        float4 v = *(float4*)(Co + r * LDC + c4);
        v.x += bias[bcol + c4 + 0];
        v.y += bias[bcol + c4 + 1];
        v.z += bias[bcol + c4 + 2];
        v.w += bias[bcol + c4 + 3];
        *(float4*)(C + (size_t)(brow + r) * N + bcol + c4) = v;
    }
}

// =====================================================================
// Persistent bi-LSTM recurrence: barrier-free tagged dataflow.
// 64 CTAs = 2 dirs x 32 grps (16 units, c = u*4+gate), 512 threads,
// register-resident W fragments. h stored as (tag<<16)|fp16 in g_ENC32;
// consumers spin on the tagged words directly. 2 syncthreads/step.
// =====================================================================
#define LDW16 520
#define LDH16 528
#define LDR 20

__device__ __forceinline__ float sigmoidf_(float x) { return 1.f / (1.f + expf(-x)); }

__global__ __launch_bounds__(512, 1) void lstm_rec(
    const float* __restrict__ whh_f, const float* __restrict__ whh_b)
{
    extern __shared__ char smx[];
    __half* wstage = (__half*)smx;                    // init only (aliases hs16+red)
    __half* hs16   = (__half*)smx;                    // [16][LDH16]
    float*  red    = (float*)(smx + 16 * LDH16 * 2);  // [16][16][LDR]

    const int tid = threadIdx.x;
    const int wid = tid >> 5;
    const int dir = blockIdx.x & 1;
    const int grp = blockIdx.x >> 1;
    const float* whh = dir ? whh_b : whh_f;
    const float* xg  = dir ? g_XGb : g_XGf;

    // stage recurrent weights fp16: wstage[c][k], c = u*4+gate
    for (int idx = tid; idx < 64 * 512; idx += 512) {
        const int c = idx >> 9, k = idx & 511;
        const int j = (c & 3) * 512 + grp * 16 + (c >> 2);
        wstage[c * LDW16 + k] = __float2half(whh[(size_t)j * 512 + k]);
    }
    __syncthreads();

    const int ntile = wid & 3;
    const int kgrp  = wid >> 2;
    wmma::fragment<wmma::matrix_b, 16, 16, 16, __half, wmma::col_major> bf[8];
#pragma unroll
    for (int kt = 0; kt < 8; ++kt)
        wmma::load_matrix_sync(bf[kt],
            wstage + (ntile * 16) * LDW16 + kgrp * 128 + kt * 16, LDW16);
    __syncthreads();

    // zero hs16 (h_{-1} = 0)
    for (int idx = tid; idx < 16 * LDH16 / 2; idx += 512)
        ((uint32_t*)hs16)[idx] = 0u;

    const int gm = tid >> 4, gu = tid & 15;   // gate threads: tid<256
    float creg = 0.f;

    // prefetch xg for step 0
    float xgr[4];
    {
        const int t0 = dir ? 1023 : 0;
        if (tid < 256) {
            const size_t xb = ((size_t)gm * 1024 + t0) * 2048 + grp * 16 + gu;
            xgr[0] = xg[xb]; xgr[1] = xg[xb + 512];
            xgr[2] = xg[xb + 1024]; xgr[3] = xg[xb + 1536];
        }
    }
    __syncthreads();

    // poll/stage roles: all 512 threads, b = tid>>5, units [k0, k0+16)
    const int pb = tid >> 5;
    const int pk = (tid & 31) * 16;

    for (int s = 0; s < 1024; ++s) {
        const int tcur  = dir ? (1023 - s) : s;
        const int tprev = dir ? (tcur + 1) : (tcur - 1);
        const int tnext = dir ? (tcur - 1) : (tcur + 1);

        // ---- poll tagged h of step s-1 and stage into smem ----
        if (s > 0) {
            const volatile uint32_t* src =
                g_ENC32 + ((size_t)pb * 1024 + tprev) * 1024 + dir * 512 + pk;
            for (;;) {
                uint32_t w[16];
                bool ok = true;
#pragma unroll
                for (int j = 0; j < 16; ++j) w[j] = src[j];
#pragma unroll
                for (int j = 0; j < 16; ++j) ok &= ((w[j] >> 16) == (unsigned)s);
                if (ok) {
                    __half* dst = hs16 + pb * LDH16 + pk;
#pragma unroll
                    for (int j = 0; j < 16; ++j)
                        dst[j] = __ushort_as_half((unsigned short)(w[j] & 0xFFFFu));
                    break;
                }
            }
        }
        __syncthreads();   // hs16 complete

        // ---- tensor matvec: 8 ldmatrix + 8 mma against register bf ----
        wmma::fragment<wmma::accumulator, 16, 16, 16, float> acc;
        wmma::fill_fragment(acc, 0.f);
#pragma unroll
        for (int kt = 0; kt < 8; ++kt) {
            wmma::fragment<wmma::matrix_a, 16, 16, 16, __half, wmma::row_major> af;
            wmma::load_matrix_sync(af, hs16 + kgrp * 128 + kt * 16, LDH16);
            wmma::mma_sync(acc, af, bf[kt], acc);
        }
        wmma::store_matrix_sync(red + wid * 16 * LDR, acc, LDR, wmma::mem_row_major);
        __syncthreads();   // red complete (also fences hs16 reads vs next stage)

        // ---- fused reduce + gates + tagged h write (256 threads) ----
        if (tid < 256) {
            const int nt = gu >> 2;
            const int nn = (gu & 3) * 4;
            float G[4];
#pragma unroll
            for (int g = 0; g < 4; ++g) {
                float sum = 0.f;
#pragma unroll
                for (int p = 0; p < 4; ++p)
                    sum += red[(p * 4 + nt) * 16 * LDR + gm * LDR + nn + g];
                G[g] = sum;
            }
            const float gi = G[0] + xgr[0];
            const float gf = G[1] + xgr[1];
            const float gg = G[2] + xgr[2];
            const float go = G[3] + xgr[3];
            const float cn = sigmoidf_(gf) * creg + sigmoidf_(gi) * tanhf(gg);
            creg = cn;
            const float hv = sigmoidf_(go) * tanhf(cn);
            const uint32_t wv = ((uint32_t)(s + 1) << 16)
                              | (uint32_t)__half_as_ushort(__float2half(hv));
            *(volatile uint32_t*)(g_ENC32
                + ((size_t)gm * 1024 + tcur) * 1024 + dir * 512 + grp * 16 + gu) = wv;
            if (s + 1 < 1024) {
                const size_t xn = ((size_t)gm * 1024 + tnext) * 2048 + grp * 16 + gu;
                xgr[0] = xg[xn]; xgr[1] = xg[xn + 512];
                xgr[2] = xg[xn + 1024]; xgr[3] = xg[xn + 1536];
            }
        }
        // no trailing sync: red is protected by the post-stage sync next step;
        // non-gate threads fall straight into the next poll (self-throttling).
    }
}

// ---------------- span mean pooling (tagged enc -> fp32) ----------------
__global__ __launch_bounds__(256) void pool_kernel(
    const int* __restrict__ heads, const int* __restrict__ tails)
{
    const int bs = blockIdx.x;
    const int b = bs >> 5;
    int lo = heads[bs] + 1, hi = tails[bs];
    if (lo < 0) lo = 0;
    if (hi > 1024) hi = 1024;
    int cnt = hi - lo; if (cnt < 1) cnt = 1;
    const float inv = 1.f / (float)cnt;
    const int h0 = threadIdx.x * 4;
    float ax = 0.f, ay = 0.f, az = 0.f, aw = 0.f;
    for (int t = lo; t < hi; ++t) {
        const uint4 v = *(const uint4*)(g_ENC32 + ((size_t)b * 1024 + t) * 1024 + h0);
        ax += __half2float(__ushort_as_half((unsigned short)(v.x & 0xFFFFu)));
        ay += __half2float(__ushort_as_half((unsigned short)(v.y & 0xFFFFu)));
        az += __half2float(__ushort_as_half((unsigned short)(v.z & 0xFFFFu)));
        aw += __half2float(__ushort_as_half((unsigned short)(v.w & 0xFFFFu)));
    }
    float4 o; o.x = ax * inv; o.y = ay * inv; o.z = az * inv; o.w = aw * inv;
    *(float4*)(g_FEATP + (size_t)bs * 1024 + h0) = o;
}

// ---------------- row LayerNorm ----------------
__global__ __launch_bounds__(256) void ln_kernel(
    const float* __restrict__ X, const float* __restrict__ R,
    const float* __restrict__ gam, const float* __restrict__ bet,
    float* __restrict__ Y)
{
    const int r = blockIdx.x;
    const int tid = threadIdx.x;
    const size_t off = (size_t)r * 1024 + tid * 4;
    float4 v = *(const float4*)(X + off);
    if (R) {
        const float4 rv = *(const float4*)(R + off);
        v.x += rv.x; v.y += rv.y; v.z += rv.z; v.w += rv.w;
    }
    float s  = v.x + v.y + v.z + v.w;
    float ss = v.x*v.x + v.y*v.y + v.z*v.z + v.w*v.w;
#pragma unroll
    for (int o = 16; o; o >>= 1) {
        s  += __shfl_xor_sync(0xffffffffu, s, o);
        ss += __shfl_xor_sync(0xffffffffu, ss, o);
    }
    __shared__ float as_[8], ass_[8];
    if ((tid & 31) == 0) { as_[tid>>5] = s; ass_[tid>>5] = ss; }
    __syncthreads();
    s = 0.f; ss = 0.f;
#pragma unroll
    for (int w = 0; w < 8; ++w) { s += as_[w]; ss += ass_[w]; }
    const float mu  = s * (1.f/1024.f);
    const float var = ss * (1.f/1024.f) - mu*mu;
    const float inv = rsqrtf(var + LN_EPS);
    const int c0 = tid * 4;
    float4 o;
    o.x = (v.x-mu)*inv*gam[c0+0] + bet[c0+0];
    o.y = (v.y-mu)*inv*gam[c0+1] + bet[c0+1];
    o.z = (v.z-mu)*inv*gam[c0+2] + bet[c0+2];
    o.w = (v.w-mu)*inv*gam[c0+3] + bet[c0+3];
    *(float4*)(Y + off) = o;
}

// ---------------- span attention ----------------
__global__ __launch_bounds__(256) void attn_kernel(const int* __restrict__ amask)
{
    const int bh = blockIdx.x;
    const int b = bh >> 4, h = bh & 15;
    __shared__ float qs[2048], ksm[2048], vsm[2048], sc[32*33];
    __shared__ int ms[32];
    const int tid = threadIdx.x;
    for (int idx = tid; idx < 2048; idx += 256) {
        const int s = idx >> 6, d = idx & 63;
        const size_t off = (size_t)(b*32 + s)*1024 + h*64 + d;
        qs[idx] = g_Qm[off]; ksm[idx] = g_Km[off]; vsm[idx] = g_Vm[off];
    }
    if (tid < 32) ms[tid] = amask[b*32 + tid];
    __syncthreads();
    for (int idx = tid; idx < 1024; idx += 256) {
        const int i = idx >> 5, j = idx & 31;
        float d0 = 0.f;
#pragma unroll
        for (int k = 0; k < 64; ++k) d0 += qs[i*64+k] * ksm[j*64+k];
        sc[i*33 + j] = d0 * 0.125f;
    }
    __syncthreads();
    const int w = tid >> 5, l = tid & 31;
    for (int i = w; i < 32; i += 8) {
        const bool valid = (ms[i] != 0) && (ms[l] != 0);
        float v = valid ? sc[i*33 + l] : -3.402823466e38f;
        float mx = v;
#pragma unroll
        for (int o = 16; o; o >>= 1) mx = fmaxf(mx, __shfl_xor_sync(0xffffffffu, mx, o));
        float e = expf(v - mx);
        float sum = e;
#pragma unroll
        for (int o = 16; o; o >>= 1) sum += __shfl_xor_sync(0xffffffffu, sum, o);
        float p = e / sum;
        if (!valid) p = 0.f;
        sc[i*33 + l] = p;
    }
    __syncthreads();
    for (int idx = tid; idx < 2048; idx += 256) {
        const int s = idx >> 6, d = idx & 63;
        float a = 0.f;
#pragma unroll
        for (int j = 0; j < 32; ++j) a += sc[s*33 + j] * vsm[j*64 + d];
        g_CTX[(size_t)(b*32 + s)*1024 + h*64 + d] = a;
    }
}

// ---------------- classifier ----------------
__global__ __launch_bounds__(96) void cls_kernel(
    const float* __restrict__ wc, const float* __restrict__ bc,
    float* __restrict__ out)
{
    const int r = blockIdx.x;
    const int lbl = threadIdx.x >> 5, lane = threadIdx.x & 31;
    const float* a = g_ATT + (size_t)r * 1024 + lane * 32;
    const float* w = wc + (size_t)lbl * 1024 + lane * 32;
    float s = 0.f;
#pragma unroll
    for (int k = 0; k < 32; ++k) s += a[k] * w[k];
#pragma unroll
    for (int o = 16; o; o >>= 1) s += __shfl_xor_sync(0xffffffffu, s, o);
    if (lane == 0) out[r * 3 + lbl] = s + bc[lbl];
}

extern "C" void kernel_launch(void* const* d_in, const int* in_sizes, int n_in,
                              void* d_out, int out_size) {
    const float* hs    = (const float*)d_in[0];
    const float* wih_f = (const float*)d_in[1];
    const float* whh_f = (const float*)d_in[2];
    const float* b_f   = (const float*)d_in[3];
    const float* wih_b = (const float*)d_in[4];
    const float* whh_b = (const float*)d_in[5];
    const float* b_b   = (const float*)d_in[6];
    const float* ln_g  = (const float*)d_in[7];
    const float* ln_b  = (const float*)d_in[8];
    const float* wq = (const float*)d_in[9];  const float* bq = (const float*)d_in[10];
    const float* wk = (const float*)d_in[11]; const float* bk = (const float*)d_in[12];
    const float* wv = (const float*)d_in[13]; const float* bv = (const float*)d_in[14];
    const float* wo = (const float*)d_in[15]; const float* bo = (const float*)d_in[16];
    const float* aln_g = (const float*)d_in[17];
    const float* aln_b = (const float*)d_in[18];
    const float* wc = (const float*)d_in[19]; const float* bc = (const float*)d_in[20];
    const int* heads = (const int*)d_in[21];
    const int* tails = (const int*)d_in[22];
    const int* amask = (const int*)d_in[23];
    float* out = (float*)d_out;

    float *XGf, *XGb, *FEATP, *FEAT, *Qm, *Km, *Vm, *CTX, *TMP, *ATT;
    __half *HS16, *WF16, *WB16, *WQ16, *WK16, *WV16, *WO16, *F16, *C16;
    cudaGetSymbolAddress((void**)&XGf, g_XGf);
    cudaGetSymbolAddress((void**)&XGb, g_XGb);
    cudaGetSymbolAddress((void**)&FEATP, g_FEATP);
    cudaGetSymbolAddress((void**)&FEAT, g_FEAT);
    cudaGetSymbolAddress((void**)&Qm, g_Qm);
    cudaGetSymbolAddress((void**)&Km, g_Km);
    cudaGetSymbolAddress((void**)&Vm, g_Vm);
    cudaGetSymbolAddress((void**)&CTX, g_CTX);
    cudaGetSymbolAddress((void**)&TMP, g_TMP);
    cudaGetSymbolAddress((void**)&ATT, g_ATT);
    cudaGetSymbolAddress((void**)&HS16, g_HS16);
    cudaGetSymbolAddress((void**)&WF16, g_WF16);
    cudaGetSymbolAddress((void**)&WB16, g_WB16);
    cudaGetSymbolAddress((void**)&WQ16, g_WQ16);
    cudaGetSymbolAddress((void**)&WK16, g_WK16);
    cudaGetSymbolAddress((void**)&WV16, g_WV16);
    cudaGetSymbolAddress((void**)&WO16, g_WO16);
    cudaGetSymbolAddress((void**)&F16,  g_F16);
    cudaGetSymbolAddress((void**)&C16,  g_C16);

    const int gsmem = 73728;
    cudaFuncSetAttribute(gemm_h, cudaFuncAttributeMaxDynamicSharedMemorySize, gsmem);

    zero_enc<<<8192, 256>>>();   // clear tags: every replay recomputes honestly

    f2h<<<16777216/2048, 256>>>(hs,    HS16, 16777216);
    f2h<<<2097152/2048,  256>>>(wih_f, WF16, 2097152);
    f2h<<<2097152/2048,  256>>>(wih_b, WB16, 2097152);
    f2h<<<1048576/2048,  256>>>(wq, WQ16, 1048576);
    f2h<<<1048576/2048,  256>>>(wk, WK16, 1048576);
    f2h<<<1048576/2048,  256>>>(wv, WV16, 1048576);
    f2h<<<1048576/2048,  256>>>(wo, WO16, 1048576);

    dim3 gXG(2048/128, 16384/128);
    gemm_h<<<gXG, 256, gsmem>>>(HS16, WF16, b_f, XGf, 16384, 2048, 1024);
    gemm_h<<<gXG, 256, gsmem>>>(HS16, WB16, b_b, XGb, 16384, 2048, 1024);

    const int lstm_smem = 64 * LDW16 * 2;   // weight stage dominates; runtime fits inside
    cudaFuncSetAttribute(lstm_rec, cudaFuncAttributeMaxDynamicSharedMemorySize, lstm_smem);
    lstm_rec<<<64, 512, lstm_smem>>>(whh_f, whh_b);

    pool_kernel<<<512, 256>>>(heads, tails);
    ln_kernel<<<512, 256>>>(FEATP, nullptr, ln_g, ln_b, FEAT);

    dim3 gP(1024/128, 512/128);
    f2h<<<524288/2048, 256>>>(FEAT, F16, 524288);
    gemm_h<<<gP, 256, gsmem>>>(F16, WQ16, bq, Qm, 512, 1024, 1024);
    gemm_h<<<gP, 256, gsmem>>>(F16, WK16, bk, Km, 512, 1024, 1024);
    gemm_h<<<gP, 256, gsmem>>>(F16, WV16, bv, Vm, 512, 1024, 1024);

    attn_kernel<<<256, 256>>>(amask);

    f2h<<<524288/2048, 256>>>(CTX, C16, 524288);
    gemm_h<<<gP, 256, gsmem>>>(C16, WO16, bo, TMP, 512, 1024, 1024);
    ln_kernel<<<512, 256>>>(TMP, FEAT, aln_g, aln_b, ATT);

    cls_kernel<<<512, 96>>>(wc, bc, out);
}

// round 14
// speedup vs baseline: 1.4103x; 1.4103x over previous
#include <cuda_runtime.h>
#include <cuda_fp16.h>
#include <mma.h>
#include <math.h>
#include <cstdint>

using namespace nvcuda;

#define LN_EPS 1e-7f

__device__ float g_XGf[(size_t)16384 * 2048];
__device__ float g_XGb[(size_t)16384 * 2048];
__device__ __half g_ENC16[(size_t)16 * 1024 * 1024];
__device__ float g_FEATP[512 * 1024];
__device__ float g_FEAT [512 * 1024];
__device__ float g_QKV[(size_t)512 * 3072];
__device__ float g_CTX[512 * 1024];
__device__ float g_TMP[512 * 1024];
__device__ float g_ATT[512 * 1024];
__device__ unsigned g_cnt[64];   // [dir*32]

// fp16 operand staging
__device__ __half g_HS16[(size_t)16384 * 1024];
__device__ __half g_WF16[(size_t)2048 * 1024];
__device__ __half g_WB16[(size_t)2048 * 1024];
__device__ __half g_WQKV16[(size_t)3072 * 1024];
__device__ __half g_WO16[(size_t)1024 * 1024];
__device__ float  g_BQKV[3072];
__device__ __half g_F16 [(size_t)512 * 1024];
__device__ __half g_C16 [(size_t)512 * 1024];

// ---------------- fp32 -> fp16 conversion ----------------
__global__ __launch_bounds__(256) void f2h(
    const float* __restrict__ x, __half* __restrict__ y, int n)
{
    const int i = (blockIdx.x * 256 + threadIdx.x) * 8;
    if (i >= n) return;
    const float4 a = *(const float4*)(x + i);
    const float4 b = *(const float4*)(x + i + 4);
    union { __half2 h2[4]; float4 v; } u;
    u.h2[0] = __floats2half2_rn(a.x, a.y);
    u.h2[1] = __floats2half2_rn(a.z, a.w);
    u.h2[2] = __floats2half2_rn(b.x, b.y);
    u.h2[3] = __floats2half2_rn(b.z, b.w);
    *(float4*)(y + i) = u.v;
}

// ---------------- concat qkv bias ----------------
__global__ __launch_bounds__(256) void cat_bias(
    const float* __restrict__ a, const float* __restrict__ b,
    const float* __restrict__ c)
{
    const int i = blockIdx.x * 256 + threadIdx.x;
    g_BQKV[i] = (i < 1024) ? a[i] : ((i < 2048) ? b[i - 1024] : c[i - 2048]);
}

// =====================================================================
// fp16 tensor GEMM (R11 version: cp.async, 2 CTAs/SM)
// =====================================================================
#define HLD 72
#define LDC 132
#define STG_A0 0
#define STG_B0 18432
#define STG_A1 36864
#define STG_B1 55296

__global__ __launch_bounds__(256, 2) void gemm_h(
    const __half* __restrict__ A, const __half* __restrict__ B,
    const float* __restrict__ bias, float* __restrict__ C,
    int M, int N, int K)
{
    extern __shared__ char smem[];
    float* Co = (float*)smem;

    const int tid = threadIdx.x;
    const int wid = tid >> 5;
    const int brow = blockIdx.y * 128;
    const int bcol = blockIdx.x * 128;
    const int wm = (wid & 3) * 32;
    const int wn = (wid >> 2) * 64;

    const __half* Ag = A + (size_t)brow * K;
    const __half* Bg = B + (size_t)bcol * K;

    wmma::fragment<wmma::accumulator, 16, 16, 16, float> acc[2][4];
#pragma unroll
    for (int i = 0; i < 2; ++i)
#pragma unroll
        for (int j = 0; j < 4; ++j) wmma::fill_fragment(acc[i][j], 0.f);

    auto issue_stage = [&](int aoff, int boff, int kt) {
#pragma unroll
        for (int p = 0; p < 4; ++p) {
            const int idx = tid + p * 256;
            const int r = idx >> 3, c = (idx & 7) * 8;
            const unsigned da = (unsigned)__cvta_generic_to_shared(
                smem + aoff + (r * HLD + c) * 2);
            const unsigned db = (unsigned)__cvta_generic_to_shared(
                smem + boff + (r * HLD + c) * 2);
            asm volatile("cp.async.cg.shared.global [%0], [%1], 16;"
                         :: "r"(da), "l"(Ag + (size_t)r * K + kt + c));
            asm volatile("cp.async.cg.shared.global [%0], [%1], 16;"
                         :: "r"(db), "l"(Bg + (size_t)r * K + kt + c));
        }
    };

    issue_stage(STG_A0, STG_B0, 0);
    asm volatile("cp.async.commit_group;");

    int buf = 0;
    for (int kt = 0; kt < K; kt += 64) {
        if (kt + 64 < K)
            issue_stage(buf ? STG_A0 : STG_A1, buf ? STG_B0 : STG_B1, kt + 64);
        asm volatile("cp.async.commit_group;");
        asm volatile("cp.async.wait_group 1;");
        __syncthreads();

        const __half* As = (const __half*)(smem + (buf ? STG_A1 : STG_A0));
        const __half* Bs = (const __half*)(smem + (buf ? STG_B1 : STG_B0));
#pragma unroll
        for (int kk = 0; kk < 64; kk += 16) {
            wmma::fragment<wmma::matrix_a, 16, 16, 16, __half, wmma::row_major> af[2];
            wmma::fragment<wmma::matrix_b, 16, 16, 16, __half, wmma::col_major> bf[4];
#pragma unroll
            for (int i = 0; i < 2; ++i)
                wmma::load_matrix_sync(af[i], As + (wm + i * 16) * HLD + kk, HLD);
#pragma unroll
            for (int j = 0; j < 4; ++j)
                wmma::load_matrix_sync(bf[j], Bs + (wn + j * 16) * HLD + kk, HLD);
#pragma unroll
            for (int i = 0; i < 2; ++i)
#pragma unroll
                for (int j = 0; j < 4; ++j)
                    wmma::mma_sync(acc[i][j], af[i], bf[j], acc[i][j]);
        }
        __syncthreads();
        buf ^= 1;
    }

#pragma unroll
    for (int i = 0; i < 2; ++i)
#pragma unroll
        for (int j = 0; j < 4; ++j)
            wmma::store_matrix_sync(Co + (wm + i * 16) * LDC + wn + j * 16,
                                    acc[i][j], LDC, wmma::mem_row_major);
    __syncthreads();

    for (int idx = tid; idx < 128 * 32; idx += 256) {
        const int r = idx >> 5, c4 = (idx & 31) * 4;
        float4 v = *(float4*)(Co + r * LDC + c4);
        v.x += bias[bcol + c4 + 0];
        v.y += bias[bcol + c4 + 1];
        v.z += bias[bcol + c4 + 2];
        v.w += bias[bcol + c4 + 3];
        *(float4*)(C + (size_t)(brow + r) * N + bcol + c4) = v;
    }
}

// =====================================================================
__global__ void bar_reset() { g_cnt[0] = 0; g_cnt[32] = 0; }

// =====================================================================
// Persistent bi-LSTM recurrence: warp-autonomous barrier protocol.
// 64 CTAs = 2 dirs x 32 grps (16 units), 512 thr = 16 warps, register-
// resident W fragments. Release: each gate warp (0-7) RED.release after
// its own h stores (target 256 arrivals/step/dir). Poll: each warp's
// lane0 polls the counter, syncwarp, stage own slice. 2 syncthreads/step.
// =====================================================================
#define LDW16 520
#define LDH16 528
#define LDR 20

__device__ __forceinline__ float sigmoidf_(float x) { return 1.f / (1.f + expf(-x)); }

__global__ __launch_bounds__(512, 1) void lstm_rec(
    const float* __restrict__ whh_f, const float* __restrict__ whh_b)
{
    extern __shared__ char smx[];
    __half* wstage = (__half*)smx;                    // init only (aliases hs16+red)
    __half* hs16   = (__half*)smx;                    // [16][LDH16]
    float*  red    = (float*)(smx + 16 * LDH16 * 2);  // [16][16][LDR]

    const int tid = threadIdx.x;
    const int wid = tid >> 5;
    const int lane = tid & 31;
    const int dir = blockIdx.x & 1;
    const int grp = blockIdx.x >> 1;
    const float* whh = dir ? whh_b : whh_f;
    const float* xg  = dir ? g_XGb : g_XGf;
    unsigned* cnt = &g_cnt[dir * 32];

    for (int idx = tid; idx < 64 * 512; idx += 512) {
        const int c = idx >> 9, k = idx & 511;
        const int j = (c & 3) * 512 + grp * 16 + (c >> 2);
        wstage[c * LDW16 + k] = __float2half(whh[(size_t)j * 512 + k]);
    }
    __syncthreads();

    const int ntile = wid & 3;
    const int kgrp  = wid >> 2;
    wmma::fragment<wmma::matrix_b, 16, 16, 16, __half, wmma::col_major> bf[8];
#pragma unroll
    for (int kt = 0; kt < 8; ++kt)
        wmma::load_matrix_sync(bf[kt],
            wstage + (ntile * 16) * LDW16 + kgrp * 128 + kt * 16, LDW16);
    __syncthreads();

    for (int idx = tid; idx < 16 * LDH16 / 2; idx += 512)
        ((uint32_t*)hs16)[idx] = 0u;

    const int gm = tid >> 4, gu = tid & 15;   // gate threads: tid<256 (warps 0-7)
    float creg = 0.f;

    float xgr[4];
    {
        const int t0 = dir ? 1023 : 0;
        if (tid < 256) {
            const size_t xb = ((size_t)gm * 1024 + t0) * 2048 + grp * 16 + gu;
            xgr[0] = xg[xb]; xgr[1] = xg[xb + 512];
            xgr[2] = xg[xb + 1024]; xgr[3] = xg[xb + 1536];
        }
    }
    __syncthreads();

    const int pb = tid >> 5;          // warp stages batch pb
    const int pk = (tid & 31) * 16;

    for (int s = 0; s < 1024; ++s) {
        const int tcur  = dir ? (1023 - s) : s;
        const int tprev = dir ? (tcur + 1) : (tcur - 1);
        const int tnext = dir ? (tcur - 1) : (tcur + 1);

        // ---- per-warp poll + stage own slice ----
        if (s > 0) {
            if (lane == 0) {
                const unsigned tgt = (unsigned)s * 256u;
                unsigned v;
                do {
                    asm volatile("ld.acquire.gpu.global.b32 %0, [%1];"
                                 : "=r"(v) : "l"(cnt));
                } while (v < tgt);
            }
            __syncwarp();
            const __half* src = g_ENC16
                + ((size_t)pb * 1024 + tprev) * 1024 + dir * 512 + pk;
            __half* dst = hs16 + pb * LDH16 + pk;
            *(uint4*)(dst)     = *(const uint4*)(src);
            *(uint4*)(dst + 8) = *(const uint4*)(src + 8);
        }
        __syncthreads();   // hs16 complete

        // ---- tensor matvec against register-resident weights ----
        wmma::fragment<wmma::accumulator, 16, 16, 16, float> acc;
        wmma::fill_fragment(acc, 0.f);
#pragma unroll
        for (int kt = 0; kt < 8; ++kt) {
            wmma::fragment<wmma::matrix_a, 16, 16, 16, __half, wmma::row_major> af;
            wmma::load_matrix_sync(af, hs16 + kgrp * 128 + kt * 16, LDH16);
            wmma::mma_sync(acc, af, bf[kt], acc);
        }
        wmma::store_matrix_sync(red + wid * 16 * LDR, acc, LDR, wmma::mem_row_major);
        __syncthreads();   // red complete; hs16 reads done

        // ---- fused reduce + gates + h write + warp release (warps 0-7) ----
        if (tid < 256) {
            const int nt = gu >> 2;
            const int nn = (gu & 3) * 4;
            float G[4];
#pragma unroll
            for (int g = 0; g < 4; ++g) {
                float sum = 0.f;
#pragma unroll
                for (int p = 0; p < 4; ++p)
                    sum += red[(p * 4 + nt) * 16 * LDR + gm * LDR + nn + g];
                G[g] = sum;
            }
            const float gi = G[0] + xgr[0];
            const float gf = G[1] + xgr[1];
            const float gg = G[2] + xgr[2];
            const float go = G[3] + xgr[3];
            const float cn = sigmoidf_(gf) * creg + sigmoidf_(gi) * tanhf(gg);
            creg = cn;
            const float hv = sigmoidf_(go) * tanhf(cn);
            g_ENC16[((size_t)gm * 1024 + tcur) * 1024 + dir * 512 + grp * 16 + gu]
                = __float2half(hv);
            if (s + 1 < 1024) {
                const size_t xn = ((size_t)gm * 1024 + tnext) * 2048 + grp * 16 + gu;
                xgr[0] = xg[xn]; xgr[1] = xg[xn + 512];
                xgr[2] = xg[xn + 1024]; xgr[3] = xg[xn + 1536];
            }
            __syncwarp();   // all lanes' h stores ordered before release
            if (lane == 0)
                asm volatile("red.release.gpu.global.add.u32 [%0], 1;"
                             :: "l"(cnt) : "memory");
        }
        // non-gate warps fall straight into the next poll (self-throttling)
    }
}

// ---------------- span mean pooling ----------------
__global__ __launch_bounds__(256) void pool_kernel(
    const int* __restrict__ heads, const int* __restrict__ tails)
{
    const int bs = blockIdx.x;
    const int b = bs >> 5;
    int lo = heads[bs] + 1, hi = tails[bs];
    if (lo < 0) lo = 0;
    if (hi > 1024) hi = 1024;
    int cnt = hi - lo; if (cnt < 1) cnt = 1;
    const float inv = 1.f / (float)cnt;
    const int h0 = threadIdx.x * 4;
    float ax = 0.f, ay = 0.f, az = 0.f, aw = 0.f;
    for (int t = lo; t < hi; ++t) {
        const uint2 v = *(const uint2*)(g_ENC16 + ((size_t)b * 1024 + t) * 1024 + h0);
        const float2 f0 = __half22float2(*(const __half2*)&v.x);
        const float2 f1 = __half22float2(*(const __half2*)&v.y);
        ax += f0.x; ay += f0.y; az += f1.x; aw += f1.y;
    }
    float4 o; o.x = ax * inv; o.y = ay * inv; o.z = az * inv; o.w = aw * inv;
    *(float4*)(g_FEATP + (size_t)bs * 1024 + h0) = o;
}

// ---------------- row LayerNorm ----------------
__global__ __launch_bounds__(256) void ln_kernel(
    const float* __restrict__ X, const float* __restrict__ R,
    const float* __restrict__ gam, const float* __restrict__ bet,
    float* __restrict__ Y)
{
    const int r = blockIdx.x;
    const int tid = threadIdx.x;
    const size_t off = (size_t)r * 1024 + tid * 4;
    float4 v = *(const float4*)(X + off);
    if (R) {
        const float4 rv = *(const float4*)(R + off);
        v.x += rv.x; v.y += rv.y; v.z += rv.z; v.w += rv.w;
    }
    float s  = v.x + v.y + v.z + v.w;
    float ss = v.x*v.x + v.y*v.y + v.z*v.z + v.w*v.w;
#pragma unroll
    for (int o = 16; o; o >>= 1) {
        s  += __shfl_xor_sync(0xffffffffu, s, o);
        ss += __shfl_xor_sync(0xffffffffu, ss, o);
    }
    __shared__ float as_[8], ass_[8];
    if ((tid & 31) == 0) { as_[tid>>5] = s; ass_[tid>>5] = ss; }
    __syncthreads();
    s = 0.f; ss = 0.f;
#pragma unroll
    for (int w = 0; w < 8; ++w) { s += as_[w]; ss += ass_[w]; }
    const float mu  = s * (1.f/1024.f);
    const float var = ss * (1.f/1024.f) - mu*mu;
    const float inv = rsqrtf(var + LN_EPS);
    const int c0 = tid * 4;
    float4 o;
    o.x = (v.x-mu)*inv*gam[c0+0] + bet[c0+0];
    o.y = (v.y-mu)*inv*gam[c0+1] + bet[c0+1];
    o.z = (v.z-mu)*inv*gam[c0+2] + bet[c0+2];
    o.w = (v.w-mu)*inv*gam[c0+3] + bet[c0+3];
    *(float4*)(Y + off) = o;
}

// ---------------- span attention (reads merged QKV, stride 3072) ----------------
__global__ __launch_bounds__(256) void attn_kernel(const int* __restrict__ amask)
{
    const int bh = blockIdx.x;
    const int b = bh >> 4, h = bh & 15;
    __shared__ float qs[2048], ksm[2048], vsm[2048], sc[32*33];
    __shared__ int ms[32];
    const int tid = threadIdx.x;
    for (int idx = tid; idx < 2048; idx += 256) {
        const int s = idx >> 6, d = idx & 63;
        const size_t off = (size_t)(b*32 + s) * 3072 + h * 64 + d;
        qs[idx]  = g_QKV[off];
        ksm[idx] = g_QKV[off + 1024];
        vsm[idx] = g_QKV[off + 2048];
    }
    if (tid < 32) ms[tid] = amask[b*32 + tid];
    __syncthreads();
    for (int idx = tid; idx < 1024; idx += 256) {
        const int i = idx >> 5, j = idx & 31;
        float d0 = 0.f;
#pragma unroll
        for (int k = 0; k < 64; ++k) d0 += qs[i*64+k] * ksm[j*64+k];
        sc[i*33 + j] = d0 * 0.125f;
    }
    __syncthreads();
    const int w = tid >> 5, l = tid & 31;
    for (int i = w; i < 32; i += 8) {
        const bool valid = (ms[i] != 0) && (ms[l] != 0);
        float v = valid ? sc[i*33 + l] : -3.402823466e38f;
        float mx = v;
#pragma unroll
        for (int o = 16; o; o >>= 1) mx = fmaxf(mx, __shfl_xor_sync(0xffffffffu, mx, o));
        float e = expf(v - mx);
        float sum = e;
#pragma unroll
        for (int o = 16; o; o >>= 1) sum += __shfl_xor_sync(0xffffffffu, sum, o);
        float p = e / sum;
        if (!valid) p = 0.f;
        sc[i*33 + l] = p;
    }
    __syncthreads();
    for (int idx = tid; idx < 2048; idx += 256) {
        const int s = idx >> 6, d = idx & 63;
        float a = 0.f;
#pragma unroll
        for (int j = 0; j < 32; ++j) a += sc[s*33 + j] * vsm[j*64 + d];
        g_CTX[(size_t)(b*32 + s)*1024 + h*64 + d] = a;
    }
}

// ---------------- classifier ----------------
__global__ __launch_bounds__(96) void cls_kernel(
    const float* __restrict__ wc, const float* __restrict__ bc,
    float* __restrict__ out)
{
    const int r = blockIdx.x;
    const int lbl = threadIdx.x >> 5, lane = threadIdx.x & 31;
    const float* a = g_ATT + (size_t)r * 1024 + lane * 32;
    const float* w = wc + (size_t)lbl * 1024 + lane * 32;
    float s = 0.f;
#pragma unroll
    for (int k = 0; k < 32; ++k) s += a[k] * w[k];
#pragma unroll
    for (int o = 16; o; o >>= 1) s += __shfl_xor_sync(0xffffffffu, s, o);
    if (lane == 0) out[r * 3 + lbl] = s + bc[lbl];
}

extern "C" void kernel_launch(void* const* d_in, const int* in_sizes, int n_in,
                              void* d_out, int out_size) {
    const float* hs    = (const float*)d_in[0];
    const float* wih_f = (const float*)d_in[1];
    const float* whh_f = (const float*)d_in[2];
    const float* b_f   = (const float*)d_in[3];
    const float* wih_b = (const float*)d_in[4];
    const float* whh_b = (const float*)d_in[5];
    const float* b_b   = (const float*)d_in[6];
    const float* ln_g  = (const float*)d_in[7];
    const float* ln_b  = (const float*)d_in[8];
    const float* wq = (const float*)d_in[9];  const float* bq = (const float*)d_in[10];
    const float* wk = (const float*)d_in[11]; const float* bk = (const float*)d_in[12];
    const float* wv = (const float*)d_in[13]; const float* bv = (const float*)d_in[14];
    const float* wo = (const float*)d_in[15]; const float* bo = (const float*)d_in[16];
    const float* aln_g = (const float*)d_in[17];
    const float* aln_b = (const float*)d_in[18];
    const float* wc = (const float*)d_in[19]; const float* bc = (const float*)d_in[20];
    const int* heads = (const int*)d_in[21];
    const int* tails = (const int*)d_in[22];
    const int* amask = (const int*)d_in[23];
    float* out = (float*)d_out;

    float *XGf, *XGb, *FEATP, *FEAT, *QKV, *CTX, *TMP, *ATT, *BQKV;
    __half *HS16, *WF16, *WB16, *WQKV16, *WO16, *F16, *C16;
    cudaGetSymbolAddress((void**)&XGf, g_XGf);
    cudaGetSymbolAddress((void**)&XGb, g_XGb);
    cudaGetSymbolAddress((void**)&FEATP, g_FEATP);
    cudaGetSymbolAddress((void**)&FEAT, g_FEAT);
    cudaGetSymbolAddress((void**)&QKV, g_QKV);
    cudaGetSymbolAddress((void**)&CTX, g_CTX);
    cudaGetSymbolAddress((void**)&TMP, g_TMP);
    cudaGetSymbolAddress((void**)&ATT, g_ATT);
    cudaGetSymbolAddress((void**)&BQKV, g_BQKV);
    cudaGetSymbolAddress((void**)&HS16, g_HS16);
    cudaGetSymbolAddress((void**)&WF16, g_WF16);
    cudaGetSymbolAddress((void**)&WB16, g_WB16);
    cudaGetSymbolAddress((void**)&WQKV16, g_WQKV16);
    cudaGetSymbolAddress((void**)&WO16, g_WO16);
    cudaGetSymbolAddress((void**)&F16,  g_F16);
    cudaGetSymbolAddress((void**)&C16,  g_C16);

    const int gsmem = 73728;
    cudaFuncSetAttribute(gemm_h, cudaFuncAttributeMaxDynamicSharedMemorySize, gsmem);

    f2h<<<16777216/2048, 256>>>(hs,    HS16, 16777216);
    f2h<<<2097152/2048,  256>>>(wih_f, WF16, 2097152);
    f2h<<<2097152/2048,  256>>>(wih_b, WB16, 2097152);
    f2h<<<1048576/2048,  256>>>(wq, WQKV16,           1048576);
    f2h<<<1048576/2048,  256>>>(wk, WQKV16 + 1048576, 1048576);
    f2h<<<1048576/2048,  256>>>(wv, WQKV16 + 2097152, 1048576);
    f2h<<<1048576/2048,  256>>>(wo, WO16, 1048576);
    cat_bias<<<12, 256>>>(bq, bk, bv);

    dim3 gXG(2048/128, 16384/128);
    gemm_h<<<gXG, 256, gsmem>>>(HS16, WF16, b_f, XGf, 16384, 2048, 1024);
    gemm_h<<<gXG, 256, gsmem>>>(HS16, WB16, b_b, XGb, 16384, 2048, 1024);

    bar_reset<<<1, 1>>>();
    const int lstm_smem = 64 * LDW16 * 2;
    cudaFuncSetAttribute(lstm_rec, cudaFuncAttributeMaxDynamicSharedMemorySize, lstm_smem);
    lstm_rec<<<64, 512, lstm_smem>>>(whh_f, whh_b);

    pool_kernel<<<512, 256>>>(heads, tails);
    ln_kernel<<<512, 256>>>(FEATP, nullptr, ln_g, ln_b, FEAT);

    f2h<<<524288/2048, 256>>>(FEAT, F16, 524288);
    dim3 gQKV(3072/128, 512/128);
    gemm_h<<<gQKV, 256, gsmem>>>(F16, WQKV16, BQKV, QKV, 512, 3072, 1024);

    attn_kernel<<<256, 256>>>(amask);

    f2h<<<524288/2048, 256>>>(CTX, C16, 524288);
    dim3 gP(1024/128, 512/128);
    gemm_h<<<gP, 256, gsmem>>>(C16, WO16, bo, TMP, 512, 1024, 1024);
    ln_kernel<<<512, 256>>>(TMP, FEAT, aln_g, aln_b, ATT);

    cls_kernel<<<512, 96>>>(wc, bc, out);
}

// round 15
// speedup vs baseline: 1.6825x; 1.1929x over previous
#include <cuda_runtime.h>
#include <cuda_fp16.h>
#include <mma.h>
#include <math.h>
#include <cstdint>

using namespace nvcuda;

#define LN_EPS 1e-7f

__device__ float g_XGf[(size_t)16384 * 2048];
__device__ float g_XGb[(size_t)16384 * 2048];
__device__ __half g_ENC16[(size_t)16 * 1024 * 1024];
__device__ float g_FEATP[512 * 1024];
__device__ float g_FEAT [512 * 1024];
__device__ float g_QKV[(size_t)512 * 3072];
__device__ float g_CTX[512 * 1024];
__device__ float g_TMP[512 * 1024];
__device__ float g_ATT[512 * 1024];
__device__ unsigned g_cnt[64];   // [dir*32]

// fp16 operand staging
__device__ __half g_HS16[(size_t)16384 * 1024];
__device__ __half g_WF16[(size_t)2048 * 1024];
__device__ __half g_WB16[(size_t)2048 * 1024];
__device__ __half g_WQKV16[(size_t)3072 * 1024];
__device__ __half g_WO16[(size_t)1024 * 1024];
__device__ float  g_BQKV[3072];
__device__ __half g_F16 [(size_t)512 * 1024];
__device__ __half g_C16 [(size_t)512 * 1024];

// ---------------- fp32 -> fp16 conversion ----------------
__global__ __launch_bounds__(256) void f2h(
    const float* __restrict__ x, __half* __restrict__ y, int n)
{
    const int i = (blockIdx.x * 256 + threadIdx.x) * 8;
    if (i >= n) return;
    const float4 a = *(const float4*)(x + i);
    const float4 b = *(const float4*)(x + i + 4);
    union { __half2 h2[4]; float4 v; } u;
    u.h2[0] = __floats2half2_rn(a.x, a.y);
    u.h2[1] = __floats2half2_rn(a.z, a.w);
    u.h2[2] = __floats2half2_rn(b.x, b.y);
    u.h2[3] = __floats2half2_rn(b.z, b.w);
    *(float4*)(y + i) = u.v;
}

// ---------------- concat qkv bias ----------------
__global__ __launch_bounds__(256) void cat_bias(
    const float* __restrict__ a, const float* __restrict__ b,
    const float* __restrict__ c)
{
    const int i = blockIdx.x * 256 + threadIdx.x;
    g_BQKV[i] = (i < 1024) ? a[i] : ((i < 2048) ? b[i - 1024] : c[i - 2048]);
}

// =====================================================================
// fp16 tensor GEMM (R11 version: cp.async, 2 CTAs/SM)
// =====================================================================
#define HLD 72
#define LDC 132
#define STG_A0 0
#define STG_B0 18432
#define STG_A1 36864
#define STG_B1 55296

__global__ __launch_bounds__(256, 2) void gemm_h(
    const __half* __restrict__ A, const __half* __restrict__ B,
    const float* __restrict__ bias, float* __restrict__ C,
    int M, int N, int K)
{
    extern __shared__ char smem[];
    float* Co = (float*)smem;

    const int tid = threadIdx.x;
    const int wid = tid >> 5;
    const int brow = blockIdx.y * 128;
    const int bcol = blockIdx.x * 128;
    const int wm = (wid & 3) * 32;
    const int wn = (wid >> 2) * 64;

    const __half* Ag = A + (size_t)brow * K;
    const __half* Bg = B + (size_t)bcol * K;

    wmma::fragment<wmma::accumulator, 16, 16, 16, float> acc[2][4];
#pragma unroll
    for (int i = 0; i < 2; ++i)
#pragma unroll
        for (int j = 0; j < 4; ++j) wmma::fill_fragment(acc[i][j], 0.f);

    auto issue_stage = [&](int aoff, int boff, int kt) {
#pragma unroll
        for (int p = 0; p < 4; ++p) {
            const int idx = tid + p * 256;
            const int r = idx >> 3, c = (idx & 7) * 8;
            const unsigned da = (unsigned)__cvta_generic_to_shared(
                smem + aoff + (r * HLD + c) * 2);
            const unsigned db = (unsigned)__cvta_generic_to_shared(
                smem + boff + (r * HLD + c) * 2);
            asm volatile("cp.async.cg.shared.global [%0], [%1], 16;"
                         :: "r"(da), "l"(Ag + (size_t)r * K + kt + c));
            asm volatile("cp.async.cg.shared.global [%0], [%1], 16;"
                         :: "r"(db), "l"(Bg + (size_t)r * K + kt + c));
        }
    };

    issue_stage(STG_A0, STG_B0, 0);
    asm volatile("cp.async.commit_group;");

    int buf = 0;
    for (int kt = 0; kt < K; kt += 64) {
        if (kt + 64 < K)
            issue_stage(buf ? STG_A0 : STG_A1, buf ? STG_B0 : STG_B1, kt + 64);
        asm volatile("cp.async.commit_group;");
        asm volatile("cp.async.wait_group 1;");
        __syncthreads();

        const __half* As = (const __half*)(smem + (buf ? STG_A1 : STG_A0));
        const __half* Bs = (const __half*)(smem + (buf ? STG_B1 : STG_B0));
#pragma unroll
        for (int kk = 0; kk < 64; kk += 16) {
            wmma::fragment<wmma::matrix_a, 16, 16, 16, __half, wmma::row_major> af[2];
            wmma::fragment<wmma::matrix_b, 16, 16, 16, __half, wmma::col_major> bf[4];
#pragma unroll
            for (int i = 0; i < 2; ++i)
                wmma::load_matrix_sync(af[i], As + (wm + i * 16) * HLD + kk, HLD);
#pragma unroll
            for (int j = 0; j < 4; ++j)
                wmma::load_matrix_sync(bf[j], Bs + (wn + j * 16) * HLD + kk, HLD);
#pragma unroll
            for (int i = 0; i < 2; ++i)
#pragma unroll
                for (int j = 0; j < 4; ++j)
                    wmma::mma_sync(acc[i][j], af[i], bf[j], acc[i][j]);
        }
        __syncthreads();
        buf ^= 1;
    }

#pragma unroll
    for (int i = 0; i < 2; ++i)
#pragma unroll
        for (int j = 0; j < 4; ++j)
            wmma::store_matrix_sync(Co + (wm + i * 16) * LDC + wn + j * 16,
                                    acc[i][j], LDC, wmma::mem_row_major);
    __syncthreads();

    for (int idx = tid; idx < 128 * 32; idx += 256) {
        const int r = idx >> 5, c4 = (idx & 31) * 4;
        float4 v = *(float4*)(Co + r * LDC + c4);
        v.x += bias[bcol + c4 + 0];
        v.y += bias[bcol + c4 + 1];
        v.z += bias[bcol + c4 + 2];
        v.w += bias[bcol + c4 + 3];
        *(float4*)(C + (size_t)(brow + r) * N + bcol + c4) = v;
    }
}

// =====================================================================
__global__ void bar_reset() { g_cnt[0] = 0; g_cnt[32] = 0; }

// =====================================================================
// Persistent bi-LSTM recurrence — R11 protocol (measured best: 2.9 ms).
// 64 CTAs = 2 dirs x 32 grps, 512 thr, register-resident W fragments.
// 1 release + 1 poll per CTA per step (tid0), 4 CTA syncs/step.
// =====================================================================
#define LDW16 520
#define LDH16 528
#define LDR 20

__device__ __forceinline__ float sigmoidf_(float x) { return 1.f / (1.f + expf(-x)); }

__global__ __launch_bounds__(512, 1) void lstm_rec(
    const float* __restrict__ whh_f, const float* __restrict__ whh_b)
{
    extern __shared__ char smx[];
    __half* wstage = (__half*)smx;                    // init only (aliases hs16+red)
    __half* hs16   = (__half*)smx;                    // [16][LDH16]
    float*  red    = (float*)(smx + 16 * LDH16 * 2);  // [16][16][LDR]

    const int tid = threadIdx.x;
    const int wid = tid >> 5;
    const int dir = blockIdx.x & 1;
    const int grp = blockIdx.x >> 1;
    const float* whh = dir ? whh_b : whh_f;
    const float* xg  = dir ? g_XGb : g_XGf;
    unsigned* cnt = &g_cnt[dir * 32];

    for (int idx = tid; idx < 64 * 512; idx += 512) {
        const int c = idx >> 9, k = idx & 511;
        const int j = (c & 3) * 512 + grp * 16 + (c >> 2);
        wstage[c * LDW16 + k] = __float2half(whh[(size_t)j * 512 + k]);
    }
    __syncthreads();

    const int ntile = wid & 3;
    const int kgrp  = wid >> 2;
    wmma::fragment<wmma::matrix_b, 16, 16, 16, __half, wmma::col_major> bf[8];
#pragma unroll
    for (int kt = 0; kt < 8; ++kt)
        wmma::load_matrix_sync(bf[kt],
            wstage + (ntile * 16) * LDW16 + kgrp * 128 + kt * 16, LDW16);
    __syncthreads();

    for (int idx = tid; idx < 16 * LDH16 / 2; idx += 512)
        ((uint32_t*)hs16)[idx] = 0u;

    const int gm = tid >> 4, gu = tid & 15;   // gate threads: tid<256
    float creg = 0.f;

    float xgr[4];
    {
        const int t0 = dir ? 1023 : 0;
        if (tid < 256) {
            const size_t xb = ((size_t)gm * 1024 + t0) * 2048 + grp * 16 + gu;
            xgr[0] = xg[xb]; xgr[1] = xg[xb + 512];
            xgr[2] = xg[xb + 1024]; xgr[3] = xg[xb + 1536];
        }
    }
    __syncthreads();

    for (int s = 0; s < 1024; ++s) {
        const int tcur  = dir ? (1023 - s) : s;
        const int tprev = dir ? (tcur + 1) : (tcur - 1);
        const int tnext = dir ? (tcur - 1) : (tcur + 1);

        // ---- stage h_prev[16][512] ----
        if (s > 0) {
            const int b  = tid >> 5;
            const int k0 = (tid & 31) * 16;
            const __half* src = g_ENC16 + ((size_t)b * 1024 + tprev) * 1024 + dir * 512 + k0;
            __half* dst = hs16 + b * LDH16 + k0;
            *(uint4*)(dst)     = *(const uint4*)(src);
            *(uint4*)(dst + 8) = *(const uint4*)(src + 8);
        }
        __syncthreads();

        // ---- tensor matvec against register-resident weights ----
        wmma::fragment<wmma::accumulator, 16, 16, 16, float> acc;
        wmma::fill_fragment(acc, 0.f);
#pragma unroll
        for (int kt = 0; kt < 8; ++kt) {
            wmma::fragment<wmma::matrix_a, 16, 16, 16, __half, wmma::row_major> af;
            wmma::load_matrix_sync(af, hs16 + kgrp * 128 + kt * 16, LDH16);
            wmma::mma_sync(acc, af, bf[kt], acc);
        }
        wmma::store_matrix_sync(red + wid * 16 * LDR, acc, LDR, wmma::mem_row_major);
        __syncthreads();

        // ---- fused reduce + gates + h write (256 threads) ----
        if (tid < 256) {
            const int nt = gu >> 2;
            const int nn = (gu & 3) * 4;
            float G[4];
#pragma unroll
            for (int g = 0; g < 4; ++g) {
                float sum = 0.f;
#pragma unroll
                for (int p = 0; p < 4; ++p)
                    sum += red[(p * 4 + nt) * 16 * LDR + gm * LDR + nn + g];
                G[g] = sum;
            }
            const float gi = G[0] + xgr[0];
            const float gf = G[1] + xgr[1];
            const float gg = G[2] + xgr[2];
            const float go = G[3] + xgr[3];
            const float cn = sigmoidf_(gf) * creg + sigmoidf_(gi) * tanhf(gg);
            creg = cn;
            const float hv = sigmoidf_(go) * tanhf(cn);
            g_ENC16[((size_t)gm * 1024 + tcur) * 1024 + dir * 512 + grp * 16 + gu]
                = __float2half(hv);
            if (s + 1 < 1024) {
                const size_t xn = ((size_t)gm * 1024 + tnext) * 2048 + grp * 16 + gu;
                xgr[0] = xg[xn]; xgr[1] = xg[xn + 512];
                xgr[2] = xg[xn + 1024]; xgr[3] = xg[xn + 1536];
            }
        }
        __syncthreads();

        // ---- release/acquire monotonic barrier (1 per CTA) ----
        if (tid == 0) {
            asm volatile("red.release.gpu.global.add.u32 [%0], 1;" :: "l"(cnt) : "memory");
            const unsigned tgt = (unsigned)(s + 1) * 32u;
            unsigned v;
            do {
                asm volatile("ld.acquire.gpu.global.b32 %0, [%1];" : "=r"(v) : "l"(cnt));
            } while (v < tgt);
        }
        __syncthreads();
    }
}

// ---------------- span mean pooling ----------------
__global__ __launch_bounds__(256) void pool_kernel(
    const int* __restrict__ heads, const int* __restrict__ tails)
{
    const int bs = blockIdx.x;
    const int b = bs >> 5;
    int lo = heads[bs] + 1, hi = tails[bs];
    if (lo < 0) lo = 0;
    if (hi > 1024) hi = 1024;
    int cnt = hi - lo; if (cnt < 1) cnt = 1;
    const float inv = 1.f / (float)cnt;
    const int h0 = threadIdx.x * 4;
    float ax = 0.f, ay = 0.f, az = 0.f, aw = 0.f;
    for (int t = lo; t < hi; ++t) {
        const uint2 v = *(const uint2*)(g_ENC16 + ((size_t)b * 1024 + t) * 1024 + h0);
        const float2 f0 = __half22float2(*(const __half2*)&v.x);
        const float2 f1 = __half22float2(*(const __half2*)&v.y);
        ax += f0.x; ay += f0.y; az += f1.x; aw += f1.y;
    }
    float4 o; o.x = ax * inv; o.y = ay * inv; o.z = az * inv; o.w = aw * inv;
    *(float4*)(g_FEATP + (size_t)bs * 1024 + h0) = o;
}

// ---------------- row LayerNorm ----------------
__global__ __launch_bounds__(256) void ln_kernel(
    const float* __restrict__ X, const float* __restrict__ R,
    const float* __restrict__ gam, const float* __restrict__ bet,
    float* __restrict__ Y)
{
    const int r = blockIdx.x;
    const int tid = threadIdx.x;
    const size_t off = (size_t)r * 1024 + tid * 4;
    float4 v = *(const float4*)(X + off);
    if (R) {
        const float4 rv = *(const float4*)(R + off);
        v.x += rv.x; v.y += rv.y; v.z += rv.z; v.w += rv.w;
    }
    float s  = v.x + v.y + v.z + v.w;
    float ss = v.x*v.x + v.y*v.y + v.z*v.z + v.w*v.w;
#pragma unroll
    for (int o = 16; o; o >>= 1) {
        s  += __shfl_xor_sync(0xffffffffu, s, o);
        ss += __shfl_xor_sync(0xffffffffu, ss, o);
    }
    __shared__ float as_[8], ass_[8];
    if ((tid & 31) == 0) { as_[tid>>5] = s; ass_[tid>>5] = ss; }
    __syncthreads();
    s = 0.f; ss = 0.f;
#pragma unroll
    for (int w = 0; w < 8; ++w) { s += as_[w]; ss += ass_[w]; }
    const float mu  = s * (1.f/1024.f);
    const float var = ss * (1.f/1024.f) - mu*mu;
    const float inv = rsqrtf(var + LN_EPS);
    const int c0 = tid * 4;
    float4 o;
    o.x = (v.x-mu)*inv*gam[c0+0] + bet[c0+0];
    o.y = (v.y-mu)*inv*gam[c0+1] + bet[c0+1];
    o.z = (v.z-mu)*inv*gam[c0+2] + bet[c0+2];
    o.w = (v.w-mu)*inv*gam[c0+3] + bet[c0+3];
    *(float4*)(Y + off) = o;
}

// ---------------- span attention (merged QKV, stride 3072) ----------------
__global__ __launch_bounds__(256) void attn_kernel(const int* __restrict__ amask)
{
    const int bh = blockIdx.x;
    const int b = bh >> 4, h = bh & 15;
    __shared__ float qs[2048], ksm[2048], vsm[2048], sc[32*33];
    __shared__ int ms[32];
    const int tid = threadIdx.x;
    for (int idx = tid; idx < 2048; idx += 256) {
        const int s = idx >> 6, d = idx & 63;
        const size_t off = (size_t)(b*32 + s) * 3072 + h * 64 + d;
        qs[idx]  = g_QKV[off];
        ksm[idx] = g_QKV[off + 1024];
        vsm[idx] = g_QKV[off + 2048];
    }
    if (tid < 32) ms[tid] = amask[b*32 + tid];
    __syncthreads();
    for (int idx = tid; idx < 1024; idx += 256) {
        const int i = idx >> 5, j = idx & 31;
        float d0 = 0.f;
#pragma unroll
        for (int k = 0; k < 64; ++k) d0 += qs[i*64+k] * ksm[j*64+k];
        sc[i*33 + j] = d0 * 0.125f;
    }
    __syncthreads();
    const int w = tid >> 5, l = tid & 31;
    for (int i = w; i < 32; i += 8) {
        const bool valid = (ms[i] != 0) && (ms[l] != 0);
        float v = valid ? sc[i*33 + l] : -3.402823466e38f;
        float mx = v;
#pragma unroll
        for (int o = 16; o; o >>= 1) mx = fmaxf(mx, __shfl_xor_sync(0xffffffffu, mx, o));
        float e = expf(v - mx);
        float sum = e;
#pragma unroll
        for (int o = 16; o; o >>= 1) sum += __shfl_xor_sync(0xffffffffu, sum, o);
        float p = e / sum;
        if (!valid) p = 0.f;
        sc[i*33 + l] = p;
    }
    __syncthreads();
    for (int idx = tid; idx < 2048; idx += 256) {
        const int s = idx >> 6, d = idx & 63;
        float a = 0.f;
#pragma unroll
        for (int j = 0; j < 32; ++j) a += sc[s*33 + j] * vsm[j*64 + d];
        g_CTX[(size_t)(b*32 + s)*1024 + h*64 + d] = a;
    }
}

// ---------------- classifier ----------------
__global__ __launch_bounds__(96) void cls_kernel(
    const float* __restrict__ wc, const float* __restrict__ bc,
    float* __restrict__ out)
{
    const int r = blockIdx.x;
    const int lbl = threadIdx.x >> 5, lane = threadIdx.x & 31;
    const float* a = g_ATT + (size_t)r * 1024 + lane * 32;
    const float* w = wc + (size_t)lbl * 1024 + lane * 32;
    float s = 0.f;
#pragma unroll
    for (int k = 0; k < 32; ++k) s += a[k] * w[k];
#pragma unroll
    for (int o = 16; o; o >>= 1) s += __shfl_xor_sync(0xffffffffu, s, o);
    if (lane == 0) out[r * 3 + lbl] = s + bc[lbl];
}

extern "C" void kernel_launch(void* const* d_in, const int* in_sizes, int n_in,
                              void* d_out, int out_size) {
    const float* hs    = (const float*)d_in[0];
    const float* wih_f = (const float*)d_in[1];
    const float* whh_f = (const float*)d_in[2];
    const float* b_f   = (const float*)d_in[3];
    const float* wih_b = (const float*)d_in[4];
    const float* whh_b = (const float*)d_in[5];
    const float* b_b   = (const float*)d_in[6];
    const float* ln_g  = (const float*)d_in[7];
    const float* ln_b  = (const float*)d_in[8];
    const float* wq = (const float*)d_in[9];  const float* bq = (const float*)d_in[10];
    const float* wk = (const float*)d_in[11]; const float* bk = (const float*)d_in[12];
    const float* wv = (const float*)d_in[13]; const float* bv = (const float*)d_in[14];
    const float* wo = (const float*)d_in[15]; const float* bo = (const float*)d_in[16];
    const float* aln_g = (const float*)d_in[17];
    const float* aln_b = (const float*)d_in[18];
    const float* wc = (const float*)d_in[19]; const float* bc = (const float*)d_in[20];
    const int* heads = (const int*)d_in[21];
    const int* tails = (const int*)d_in[22];
    const int* amask = (const int*)d_in[23];
    float* out = (float*)d_out;

    float *XGf, *XGb, *FEATP, *FEAT, *QKV, *CTX, *TMP, *ATT, *BQKV;
    __half *HS16, *WF16, *WB16, *WQKV16, *WO16, *F16, *C16;
    cudaGetSymbolAddress((void**)&XGf, g_XGf);
    cudaGetSymbolAddress((void**)&XGb, g_XGb);
    cudaGetSymbolAddress((void**)&FEATP, g_FEATP);
    cudaGetSymbolAddress((void**)&FEAT, g_FEAT);
    cudaGetSymbolAddress((void**)&QKV, g_QKV);
    cudaGetSymbolAddress((void**)&CTX, g_CTX);
    cudaGetSymbolAddress((void**)&TMP, g_TMP);
    cudaGetSymbolAddress((void**)&ATT, g_ATT);
    cudaGetSymbolAddress((void**)&BQKV, g_BQKV);
    cudaGetSymbolAddress((void**)&HS16, g_HS16);
    cudaGetSymbolAddress((void**)&WF16, g_WF16);
    cudaGetSymbolAddress((void**)&WB16, g_WB16);
    cudaGetSymbolAddress((void**)&WQKV16, g_WQKV16);
    cudaGetSymbolAddress((void**)&WO16, g_WO16);
    cudaGetSymbolAddress((void**)&F16,  g_F16);
    cudaGetSymbolAddress((void**)&C16,  g_C16);

    const int gsmem = 73728;
    cudaFuncSetAttribute(gemm_h, cudaFuncAttributeMaxDynamicSharedMemorySize, gsmem);

    f2h<<<16777216/2048, 256>>>(hs,    HS16, 16777216);
    f2h<<<2097152/2048,  256>>>(wih_f, WF16, 2097152);
    f2h<<<2097152/2048,  256>>>(wih_b, WB16, 2097152);
    f2h<<<1048576/2048,  256>>>(wq, WQKV16,           1048576);
    f2h<<<1048576/2048,  256>>>(wk, WQKV16 + 1048576, 1048576);
    f2h<<<1048576/2048,  256>>>(wv, WQKV16 + 2097152, 1048576);
    f2h<<<1048576/2048,  256>>>(wo, WO16, 1048576);
    cat_bias<<<12, 256>>>(bq, bk, bv);

    dim3 gXG(2048/128, 16384/128);
    gemm_h<<<gXG, 256, gsmem>>>(HS16, WF16, b_f, XGf, 16384, 2048, 1024);
    gemm_h<<<gXG, 256, gsmem>>>(HS16, WB16, b_b, XGb, 16384, 2048, 1024);

    bar_reset<<<1, 1>>>();
    const int lstm_smem = 64 * LDW16 * 2;
    cudaFuncSetAttribute(lstm_rec, cudaFuncAttributeMaxDynamicSharedMemorySize, lstm_smem);
    lstm_rec<<<64, 512, lstm_smem>>>(whh_f, whh_b);

    pool_kernel<<<512, 256>>>(heads, tails);
    ln_kernel<<<512, 256>>>(FEATP, nullptr, ln_g, ln_b, FEAT);

    f2h<<<524288/2048, 256>>>(FEAT, F16, 524288);
    dim3 gQKV(3072/128, 512/128);
    gemm_h<<<gQKV, 256, gsmem>>>(F16, WQKV16, BQKV, QKV, 512, 3072, 1024);

    attn_kernel<<<256, 256>>>(amask);

    f2h<<<524288/2048, 256>>>(CTX, C16, 524288);
    dim3 gP(1024/128, 512/128);
    gemm_h<<<gP, 256, gsmem>>>(C16, WO16, bo, TMP, 512, 1024, 1024);
    ln_kernel<<<512, 256>>>(TMP, FEAT, aln_g, aln_b, ATT);

    cls_kernel<<<512, 96>>>(wc, bc, out);
}

// round 16
// speedup vs baseline: 1.7273x; 1.0266x over previous
#include <cuda_runtime.h>
#include <cuda_fp16.h>
#include <mma.h>
#include <math.h>
#include <cstdint>

using namespace nvcuda;

#define LN_EPS 1e-7f

__device__ float g_XGf[(size_t)16384 * 2048];
__device__ float g_XGb[(size_t)16384 * 2048];
__device__ __half g_ENC16[(size_t)16 * 1024 * 1024];
__device__ float g_FEATP[512 * 1024];
__device__ float g_FEAT [512 * 1024];
__device__ float g_QKV[(size_t)512 * 3072];
__device__ float g_CTX[512 * 1024];
__device__ float g_TMP[512 * 1024];
__device__ float g_ATT[512 * 1024];
__device__ unsigned g_cnt[64];   // [dir*32]

// fp16 operand staging
__device__ __half g_HS16[(size_t)16384 * 1024];
__device__ __half g_WF16[(size_t)2048 * 1024];
__device__ __half g_WB16[(size_t)2048 * 1024];
__device__ __half g_WQKV16[(size_t)3072 * 1024];
__device__ __half g_WO16[(size_t)1024 * 1024];
__device__ float  g_BQKV[3072];
__device__ __half g_F16 [(size_t)512 * 1024];
__device__ __half g_C16 [(size_t)512 * 1024];

// ---------------- fp32 -> fp16 conversion ----------------
__global__ __launch_bounds__(256) void f2h(
    const float* __restrict__ x, __half* __restrict__ y, int n)
{
    const int i = (blockIdx.x * 256 + threadIdx.x) * 8;
    if (i >= n) return;
    const float4 a = *(const float4*)(x + i);
    const float4 b = *(const float4*)(x + i + 4);
    union { __half2 h2[4]; float4 v; } u;
    u.h2[0] = __floats2half2_rn(a.x, a.y);
    u.h2[1] = __floats2half2_rn(a.z, a.w);
    u.h2[2] = __floats2half2_rn(b.x, b.y);
    u.h2[3] = __floats2half2_rn(b.z, b.w);
    *(float4*)(y + i) = u.v;
}

// ---------------- concat qkv bias ----------------
__global__ __launch_bounds__(256) void cat_bias(
    const float* __restrict__ a, const float* __restrict__ b,
    const float* __restrict__ c)
{
    const int i = blockIdx.x * 256 + threadIdx.x;
    g_BQKV[i] = (i < 1024) ? a[i] : ((i < 2048) ? b[i - 1024] : c[i - 2048]);
}

// =====================================================================
// fp16 tensor GEMM (R11 version: cp.async, 2 CTAs/SM)
// =====================================================================
#define HLD 72
#define LDC 132
#define STG_A0 0
#define STG_B0 18432
#define STG_A1 36864
#define STG_B1 55296

__global__ __launch_bounds__(256, 2) void gemm_h(
    const __half* __restrict__ A, const __half* __restrict__ B,
    const float* __restrict__ bias, float* __restrict__ C,
    int M, int N, int K)
{
    extern __shared__ char smem[];
    float* Co = (float*)smem;

    const int tid = threadIdx.x;
    const int wid = tid >> 5;
    const int brow = blockIdx.y * 128;
    const int bcol = blockIdx.x * 128;
    const int wm = (wid & 3) * 32;
    const int wn = (wid >> 2) * 64;

    const __half* Ag = A + (size_t)brow * K;
    const __half* Bg = B + (size_t)bcol * K;

    wmma::fragment<wmma::accumulator, 16, 16, 16, float> acc[2][4];
#pragma unroll
    for (int i = 0; i < 2; ++i)
#pragma unroll
        for (int j = 0; j < 4; ++j) wmma::fill_fragment(acc[i][j], 0.f);

    auto issue_stage = [&](int aoff, int boff, int kt) {
#pragma unroll
        for (int p = 0; p < 4; ++p) {
            const int idx = tid + p * 256;
            const int r = idx >> 3, c = (idx & 7) * 8;
            const unsigned da = (unsigned)__cvta_generic_to_shared(
                smem + aoff + (r * HLD + c) * 2);
            const unsigned db = (unsigned)__cvta_generic_to_shared(
                smem + boff + (r * HLD + c) * 2);
            asm volatile("cp.async.cg.shared.global [%0], [%1], 16;"
                         :: "r"(da), "l"(Ag + (size_t)r * K + kt + c));
            asm volatile("cp.async.cg.shared.global [%0], [%1], 16;"
                         :: "r"(db), "l"(Bg + (size_t)r * K + kt + c));
        }
    };

    issue_stage(STG_A0, STG_B0, 0);
    asm volatile("cp.async.commit_group;");

    int buf = 0;
    for (int kt = 0; kt < K; kt += 64) {
        if (kt + 64 < K)
            issue_stage(buf ? STG_A0 : STG_A1, buf ? STG_B0 : STG_B1, kt + 64);
        asm volatile("cp.async.commit_group;");
        asm volatile("cp.async.wait_group 1;");
        __syncthreads();

        const __half* As = (const __half*)(smem + (buf ? STG_A1 : STG_A0));
        const __half* Bs = (const __half*)(smem + (buf ? STG_B1 : STG_B0));
#pragma unroll
        for (int kk = 0; kk < 64; kk += 16) {
            wmma::fragment<wmma::matrix_a, 16, 16, 16, __half, wmma::row_major> af[2];
            wmma::fragment<wmma::matrix_b, 16, 16, 16, __half, wmma::col_major> bf[4];
#pragma unroll
            for (int i = 0; i < 2; ++i)
                wmma::load_matrix_sync(af[i], As + (wm + i * 16) * HLD + kk, HLD);
#pragma unroll
            for (int j = 0; j < 4; ++j)
                wmma::load_matrix_sync(bf[j], Bs + (wn + j * 16) * HLD + kk, HLD);
#pragma unroll
            for (int i = 0; i < 2; ++i)
#pragma unroll
                for (int j = 0; j < 4; ++j)
                    wmma::mma_sync(acc[i][j], af[i], bf[j], acc[i][j]);
        }
        __syncthreads();
        buf ^= 1;
    }

#pragma unroll
    for (int i = 0; i < 2; ++i)
#pragma unroll
        for (int j = 0; j < 4; ++j)
            wmma::store_matrix_sync(Co + (wm + i * 16) * LDC + wn + j * 16,
                                    acc[i][j], LDC, wmma::mem_row_major);
    __syncthreads();

    for (int idx = tid; idx < 128 * 32; idx += 256) {
        const int r = idx >> 5, c4 = (idx & 31) * 4;
        float4 v = *(float4*)(Co + r * LDC + c4);
        v.x += bias[bcol + c4 + 0];
        v.y += bias[bcol + c4 + 1];
        v.z += bias[bcol + c4 + 2];
        v.w += bias[bcol + c4 + 3];
        *(float4*)(C + (size_t)(brow + r) * N + bcol + c4) = v;
    }
}

// =====================================================================
__global__ void bar_reset() { g_cnt[0] = 0; g_cnt[32] = 0; }

// =====================================================================
// Persistent bi-LSTM recurrence — R11 protocol + per-warp poll + MUFU gates.
// 64 CTAs = 2 dirs x 32 grps, 512 thr, register-resident W fragments.
// 1 release per CTA (tid0); poll by each warp's lane0 at loop head.
// 3 CTA syncs/step.
// =====================================================================
#define LDW16 520
#define LDH16 528
#define LDR 20

__device__ __forceinline__ float fsig(float x) { return 0.5f * __tanhf(0.5f * x) + 0.5f; }

__global__ __launch_bounds__(512, 1) void lstm_rec(
    const float* __restrict__ whh_f, const float* __restrict__ whh_b)
{
    extern __shared__ char smx[];
    __half* wstage = (__half*)smx;                    // init only (aliases hs16+red)
    __half* hs16   = (__half*)smx;                    // [16][LDH16]
    float*  red    = (float*)(smx + 16 * LDH16 * 2);  // [16][16][LDR]

    const int tid = threadIdx.x;
    const int wid = tid >> 5;
    const int lane = tid & 31;
    const int dir = blockIdx.x & 1;
    const int grp = blockIdx.x >> 1;
    const float* whh = dir ? whh_b : whh_f;
    const float* xg  = dir ? g_XGb : g_XGf;
    unsigned* cnt = &g_cnt[dir * 32];

    for (int idx = tid; idx < 64 * 512; idx += 512) {
        const int c = idx >> 9, k = idx & 511;
        const int j = (c & 3) * 512 + grp * 16 + (c >> 2);
        wstage[c * LDW16 + k] = __float2half(whh[(size_t)j * 512 + k]);
    }
    __syncthreads();

    const int ntile = wid & 3;
    const int kgrp  = wid >> 2;
    wmma::fragment<wmma::matrix_b, 16, 16, 16, __half, wmma::col_major> bf[8];
#pragma unroll
    for (int kt = 0; kt < 8; ++kt)
        wmma::load_matrix_sync(bf[kt],
            wstage + (ntile * 16) * LDW16 + kgrp * 128 + kt * 16, LDW16);
    __syncthreads();

    for (int idx = tid; idx < 16 * LDH16 / 2; idx += 512)
        ((uint32_t*)hs16)[idx] = 0u;

    const int gm = tid >> 4, gu = tid & 15;   // gate threads: tid<256
    float creg = 0.f;

    float xgr[4];
    {
        const int t0 = dir ? 1023 : 0;
        if (tid < 256) {
            const size_t xb = ((size_t)gm * 1024 + t0) * 2048 + grp * 16 + gu;
            xgr[0] = xg[xb]; xgr[1] = xg[xb + 512];
            xgr[2] = xg[xb + 1024]; xgr[3] = xg[xb + 1536];
        }
    }
    __syncthreads();

    const int pb = tid >> 5;          // warp stages batch pb
    const int pk = (tid & 31) * 16;

    for (int s = 0; s < 1024; ++s) {
        const int tcur  = dir ? (1023 - s) : s;
        const int tprev = dir ? (tcur + 1) : (tcur - 1);
        const int tnext = dir ? (tcur - 1) : (tcur + 1);

        // ---- per-warp poll + stage own slice (single-word acquire poll) ----
        if (s > 0) {
            if (lane == 0) {
                const unsigned tgt = (unsigned)s * 32u;
                unsigned v;
                do {
                    asm volatile("ld.acquire.gpu.global.b32 %0, [%1];"
                                 : "=r"(v) : "l"(cnt));
                } while (v < tgt);
            }
            __syncwarp();
            const __half* src = g_ENC16 + ((size_t)pb * 1024 + tprev) * 1024 + dir * 512 + pk;
            __half* dst = hs16 + pb * LDH16 + pk;
            *(uint4*)(dst)     = *(const uint4*)(src);
            *(uint4*)(dst + 8) = *(const uint4*)(src + 8);
        }
        __syncthreads();   // hs16 complete

        // ---- tensor matvec against register-resident weights ----
        wmma::fragment<wmma::accumulator, 16, 16, 16, float> acc;
        wmma::fill_fragment(acc, 0.f);
#pragma unroll
        for (int kt = 0; kt < 8; ++kt) {
            wmma::fragment<wmma::matrix_a, 16, 16, 16, __half, wmma::row_major> af;
            wmma::load_matrix_sync(af, hs16 + kgrp * 128 + kt * 16, LDH16);
            wmma::mma_sync(acc, af, bf[kt], acc);
        }
        wmma::store_matrix_sync(red + wid * 16 * LDR, acc, LDR, wmma::mem_row_major);
        __syncthreads();   // red complete; hs16 reads done

        // ---- fused reduce + gates + h write (256 threads), MUFU tanh ----
        if (tid < 256) {
            const int nt = gu >> 2;
            const int nn = (gu & 3) * 4;
            float G[4];
#pragma unroll
            for (int g = 0; g < 4; ++g) {
                float sum = 0.f;
#pragma unroll
                for (int p = 0; p < 4; ++p)
                    sum += red[(p * 4 + nt) * 16 * LDR + gm * LDR + nn + g];
                G[g] = sum;
            }
            const float gi = G[0] + xgr[0];
            const float gf = G[1] + xgr[1];
            const float gg = G[2] + xgr[2];
            const float go = G[3] + xgr[3];
            const float cn = fsig(gf) * creg + fsig(gi) * __tanhf(gg);
            creg = cn;
            const float hv = fsig(go) * __tanhf(cn);
            g_ENC16[((size_t)gm * 1024 + tcur) * 1024 + dir * 512 + grp * 16 + gu]
                = __float2half(hv);
            if (s + 1 < 1024) {
                const size_t xn = ((size_t)gm * 1024 + tnext) * 2048 + grp * 16 + gu;
                xgr[0] = xg[xn]; xgr[1] = xg[xn + 512];
                xgr[2] = xg[xn + 1024]; xgr[3] = xg[xn + 1536];
            }
        }
        __syncthreads();   // all h stores done

        // ---- single release per CTA; poll happens at next loop head ----
        if (tid == 0)
            asm volatile("red.release.gpu.global.add.u32 [%0], 1;"
                         :: "l"(cnt) : "memory");
    }
}

// ---------------- span mean pooling ----------------
__global__ __launch_bounds__(256) void pool_kernel(
    const int* __restrict__ heads, const int* __restrict__ tails)
{
    const int bs = blockIdx.x;
    const int b = bs >> 5;
    int lo = heads[bs] + 1, hi = tails[bs];
    if (lo < 0) lo = 0;
    if (hi > 1024) hi = 1024;
    int cnt = hi - lo; if (cnt < 1) cnt = 1;
    const float inv = 1.f / (float)cnt;
    const int h0 = threadIdx.x * 4;
    float ax = 0.f, ay = 0.f, az = 0.f, aw = 0.f;
    for (int t = lo; t < hi; ++t) {
        const uint2 v = *(const uint2*)(g_ENC16 + ((size_t)b * 1024 + t) * 1024 + h0);
        const float2 f0 = __half22float2(*(const __half2*)&v.x);
        const float2 f1 = __half22float2(*(const __half2*)&v.y);
        ax += f0.x; ay += f0.y; az += f1.x; aw += f1.y;
    }
    float4 o; o.x = ax * inv; o.y = ay * inv; o.z = az * inv; o.w = aw * inv;
    *(float4*)(g_FEATP + (size_t)bs * 1024 + h0) = o;
}

// ---------------- row LayerNorm ----------------
__global__ __launch_bounds__(256) void ln_kernel(
    const float* __restrict__ X, const float* __restrict__ R,
    const float* __restrict__ gam, const float* __restrict__ bet,
    float* __restrict__ Y)
{
    const int r = blockIdx.x;
    const int tid = threadIdx.x;
    const size_t off = (size_t)r * 1024 + tid * 4;
    float4 v = *(const float4*)(X + off);
    if (R) {
        const float4 rv = *(const float4*)(R + off);
        v.x += rv.x; v.y += rv.y; v.z += rv.z; v.w += rv.w;
    }
    float s  = v.x + v.y + v.z + v.w;
    float ss = v.x*v.x + v.y*v.y + v.z*v.z + v.w*v.w;
#pragma unroll
    for (int o = 16; o; o >>= 1) {
        s  += __shfl_xor_sync(0xffffffffu, s, o);
        ss += __shfl_xor_sync(0xffffffffu, ss, o);
    }
    __shared__ float as_[8], ass_[8];
    if ((tid & 31) == 0) { as_[tid>>5] = s; ass_[tid>>5] = ss; }
    __syncthreads();
    s = 0.f; ss = 0.f;
#pragma unroll
    for (int w = 0; w < 8; ++w) { s += as_[w]; ss += ass_[w]; }
    const float mu  = s * (1.f/1024.f);
    const float var = ss * (1.f/1024.f) - mu*mu;
    const float inv = rsqrtf(var + LN_EPS);
    const int c0 = tid * 4;
    float4 o;
    o.x = (v.x-mu)*inv*gam[c0+0] + bet[c0+0];
    o.y = (v.y-mu)*inv*gam[c0+1] + bet[c0+1];
    o.z = (v.z-mu)*inv*gam[c0+2] + bet[c0+2];
    o.w = (v.w-mu)*inv*gam[c0+3] + bet[c0+3];
    *(float4*)(Y + off) = o;
}

// ---------------- span attention (merged QKV, stride 3072) ----------------
__global__ __launch_bounds__(256) void attn_kernel(const int* __restrict__ amask)
{
    const int bh = blockIdx.x;
    const int b = bh >> 4, h = bh & 15;
    __shared__ float qs[2048], ksm[2048], vsm[2048], sc[32*33];
    __shared__ int ms[32];
    const int tid = threadIdx.x;
    for (int idx = tid; idx < 2048; idx += 256) {
        const int s = idx >> 6, d = idx & 63;
        const size_t off = (size_t)(b*32 + s) * 3072 + h * 64 + d;
        qs[idx]  = g_QKV[off];
        ksm[idx] = g_QKV[off + 1024];
        vsm[idx] = g_QKV[off + 2048];
    }
    if (tid < 32) ms[tid] = amask[b*32 + tid];
    __syncthreads();
    for (int idx = tid; idx < 1024; idx += 256) {
        const int i = idx >> 5, j = idx & 31;
        float d0 = 0.f;
#pragma unroll
        for (int k = 0; k < 64; ++k) d0 += qs[i*64+k] * ksm[j*64+k];
        sc[i*33 + j] = d0 * 0.125f;
    }
    __syncthreads();
    const int w = tid >> 5, l = tid & 31;
    for (int i = w; i < 32; i += 8) {
        const bool valid = (ms[i] != 0) && (ms[l] != 0);
        float v = valid ? sc[i*33 + l] : -3.402823466e38f;
        float mx = v;
#pragma unroll
        for (int o = 16; o; o >>= 1) mx = fmaxf(mx, __shfl_xor_sync(0xffffffffu, mx, o));
        float e = expf(v - mx);
        float sum = e;
#pragma unroll
        for (int o = 16; o; o >>= 1) sum += __shfl_xor_sync(0xffffffffu, sum, o);
        float p = e / sum;
        if (!valid) p = 0.f;
        sc[i*33 + l] = p;
    }
    __syncthreads();
    for (int idx = tid; idx < 2048; idx += 256) {
        const int s = idx >> 6, d = idx & 63;
        float a = 0.f;
#pragma unroll
        for (int j = 0; j < 32; ++j) a += sc[s*33 + j] * vsm[j*64 + d];
        g_CTX[(size_t)(b*32 + s)*1024 + h*64 + d] = a;
    }
}

// ---------------- classifier ----------------
__global__ __launch_bounds__(96) void cls_kernel(
    const float* __restrict__ wc, const float* __restrict__ bc,
    float* __restrict__ out)
{
    const int r = blockIdx.x;
    const int lbl = threadIdx.x >> 5, lane = threadIdx.x & 31;
    const float* a = g_ATT + (size_t)r * 1024 + lane * 32;
    const float* w = wc + (size_t)lbl * 1024 + lane * 32;
    float s = 0.f;
#pragma unroll
    for (int k = 0; k < 32; ++k) s += a[k] * w[k];
#pragma unroll
    for (int o = 16; o; o >>= 1) s += __shfl_xor_sync(0xffffffffu, s, o);
    if (lane == 0) out[r * 3 + lbl] = s + bc[lbl];
}

extern "C" void kernel_launch(void* const* d_in, const int* in_sizes, int n_in,
                              void* d_out, int out_size) {
    const float* hs    = (const float*)d_in[0];
    const float* wih_f = (const float*)d_in[1];
    const float* whh_f = (const float*)d_in[2];
    const float* b_f   = (const float*)d_in[3];
    const float* wih_b = (const float*)d_in[4];
    const float* whh_b = (const float*)d_in[5];
    const float* b_b   = (const float*)d_in[6];
    const float* ln_g  = (const float*)d_in[7];
    const float* ln_b  = (const float*)d_in[8];
    const float* wq = (const float*)d_in[9];  const float* bq = (const float*)d_in[10];
    const float* wk = (const float*)d_in[11]; const float* bk = (const float*)d_in[12];
    const float* wv = (const float*)d_in[13]; const float* bv = (const float*)d_in[14];
    const float* wo = (const float*)d_in[15]; const float* bo = (const float*)d_in[16];
    const float* aln_g = (const float*)d_in[17];
    const float* aln_b = (const float*)d_in[18];
    const float* wc = (const float*)d_in[19]; const float* bc = (const float*)d_in[20];
    const int* heads = (const int*)d_in[21];
    const int* tails = (const int*)d_in[22];
    const int* amask = (const int*)d_in[23];
    float* out = (float*)d_out;

    float *XGf, *XGb, *FEATP, *FEAT, *QKV, *CTX, *TMP, *ATT, *BQKV;
    __half *HS16, *WF16, *WB16, *WQKV16, *WO16, *F16, *C16;
    cudaGetSymbolAddress((void**)&XGf, g_XGf);
    cudaGetSymbolAddress((void**)&XGb, g_XGb);
    cudaGetSymbolAddress((void**)&FEATP, g_FEATP);
    cudaGetSymbolAddress((void**)&FEAT, g_FEAT);
    cudaGetSymbolAddress((void**)&QKV, g_QKV);
    cudaGetSymbolAddress((void**)&CTX, g_CTX);
    cudaGetSymbolAddress((void**)&TMP, g_TMP);
    cudaGetSymbolAddress((void**)&ATT, g_ATT);
    cudaGetSymbolAddress((void**)&BQKV, g_BQKV);
    cudaGetSymbolAddress((void**)&HS16, g_HS16);
    cudaGetSymbolAddress((void**)&WF16, g_WF16);
    cudaGetSymbolAddress((void**)&WB16, g_WB16);
    cudaGetSymbolAddress((void**)&WQKV16, g_WQKV16);
    cudaGetSymbolAddress((void**)&WO16, g_WO16);
    cudaGetSymbolAddress((void**)&F16,  g_F16);
    cudaGetSymbolAddress((void**)&C16,  g_C16);

    const int gsmem = 73728;
    cudaFuncSetAttribute(gemm_h, cudaFuncAttributeMaxDynamicSharedMemorySize, gsmem);

    bar_reset<<<1, 1>>>();
    f2h<<<16777216/2048, 256>>>(hs,    HS16, 16777216);
    f2h<<<2097152/2048,  256>>>(wih_f, WF16, 2097152);
    f2h<<<2097152/2048,  256>>>(wih_b, WB16, 2097152);
    f2h<<<1048576/2048,  256>>>(wq, WQKV16,           1048576);
    f2h<<<1048576/2048,  256>>>(wk, WQKV16 + 1048576, 1048576);
    f2h<<<1048576/2048,  256>>>(wv, WQKV16 + 2097152, 1048576);
    f2h<<<1048576/2048,  256>>>(wo, WO16, 1048576);
    cat_bias<<<12, 256>>>(bq, bk, bv);

    dim3 gXG(2048/128, 16384/128);
    gemm_h<<<gXG, 256, gsmem>>>(HS16, WF16, b_f, XGf, 16384, 2048, 1024);
    gemm_h<<<gXG, 256, gsmem>>>(HS16, WB16, b_b, XGb, 16384, 2048, 1024);

    const int lstm_smem = 64 * LDW16 * 2;
    cudaFuncSetAttribute(lstm_rec, cudaFuncAttributeMaxDynamicSharedMemorySize, lstm_smem);
    lstm_rec<<<64, 512, lstm_smem>>>(whh_f, whh_b);

    pool_kernel<<<512, 256>>>(heads, tails);
    ln_kernel<<<512, 256>>>(FEATP, nullptr, ln_g, ln_b, FEAT);

    f2h<<<524288/2048, 256>>>(FEAT, F16, 524288);
    dim3 gQKV(3072/128, 512/128);
    gemm_h<<<gQKV, 256, gsmem>>>(F16, WQKV16, BQKV, QKV, 512, 3072, 1024);

    attn_kernel<<<256, 256>>>(amask);

    f2h<<<524288/2048, 256>>>(CTX, C16, 524288);
    dim3 gP(1024/128, 512/128);
    gemm_h<<<gP, 256, gsmem>>>(C16, WO16, bo, TMP, 512, 1024, 1024);
    ln_kernel<<<512, 256>>>(TMP, FEAT, aln_g, aln_b, ATT);

    cls_kernel<<<512, 96>>>(wc, bc, out);
}